// round 12
// baseline (speedup 1.0000x reference)
#include <cuda_runtime.h>
#include <math_constants.h>

#define H      512
#define NMAX   262144
#define BMAX   4096
#define K1ROWS 8
#define K1GRID (NMAX / K1ROWS)
#define CHUNK  64

// ---- scratch (no allocations allowed) ----
__device__ float d_logits[NMAX];
__device__ float d_blockmax[K1GRID];
__device__ float d_blocksum[K1GRID];
__device__ int   d_segstart[BMAX + 1];
__device__ float d_gmax;
__device__ float d_invZ;

// Segment starts from sorted batch ids. dtype sniff: n even -> int32-view
// elem n-1 is an int64 high word (==0) iff dtype is int64; else it's B-1 != 0.
__global__ void __launch_bounds__(256) k_seg(const void* __restrict__ batch,
                                             int n, int B) {
    int i = blockIdx.x * 256 + threadIdx.x;
    if (i >= n) return;
    int is64 = (((const int*)batch)[n - 1] == 0);   // broadcast L2 hit
    int bc, bp;
    if (is64) {
        bc = (int)__ldg(((const long long*)batch) + i);
        bp = (i == 0) ? -1 : (int)__ldg(((const long long*)batch) + i - 1);
    } else {
        bc = __ldg(((const int*)batch) + i);
        bp = (i == 0) ? -1 : __ldg(((const int*)batch) + i - 1);
    }
    if (bc != bp) d_segstart[bc] = i;
    if (i == n - 1) d_segstart[B] = n;
}

// Per row: logit = x[row,:] . W  (bias cancels in the global softmax).
// Per block: blockmax + sum(exp(l - blockmax))  (log-sum-exp partials).
// Clean streaming kernel — nothing else rides along. (84.7% DRAM measured.)
__global__ void __launch_bounds__(256) k_logits(const float* __restrict__ x,
                                                const float* __restrict__ W, int n) {
    __shared__ float sW[H];
    __shared__ float smax[K1ROWS];
    int tid = threadIdx.x;
    sW[tid]       = W[tid];
    sW[tid + 256] = W[tid + 256];
    __syncthreads();

    int warp = tid >> 5, lane = tid & 31;
    int row  = blockIdx.x * K1ROWS + warp;
    float v = -CUDART_INF_F;
    if (row < n) {
        const float4* xr = (const float4*)(x + (size_t)row * H);
        const float4* w4 = (const float4*)sW;
        float acc = 0.0f;
        #pragma unroll
        for (int k = 0; k < 4; k++) {
            float4 a = __ldcs(&xr[lane + 32 * k]);   // streaming: no L2 reuse possible
            float4 w = w4[lane + 32 * k];
            acc += a.x * w.x + a.y * w.y + a.z * w.z + a.w * w.w;
        }
        #pragma unroll
        for (int o = 16; o; o >>= 1) acc += __shfl_xor_sync(0xffffffffu, acc, o);
        if (lane == 0) d_logits[row] = acc;
        v = acc;
    }
    if (lane == 0) smax[warp] = v;
    __syncthreads();
    if (tid == 0) {
        float m = smax[0];
        #pragma unroll
        for (int i = 1; i < K1ROWS; i++) m = fmaxf(m, smax[i]);
        float s = 0.0f;
        if (m > -CUDART_INF_F) {
            #pragma unroll
            for (int i = 0; i < K1ROWS; i++) s += __expf(smax[i] - m);
        }
        d_blockmax[blockIdx.x] = m;
        d_blocksum[blockIdx.x] = s;
    }
}

// gmax = max blockmax;  Z = sum blocksum_j * exp(blockmax_j - gmax)
__global__ void __launch_bounds__(1024) k_reduce(int nb) {
    __shared__ float sm[1024];
    float m = -CUDART_INF_F;
    for (int i = threadIdx.x; i < nb; i += 1024) m = fmaxf(m, d_blockmax[i]);
    sm[threadIdx.x] = m;
    __syncthreads();
    #pragma unroll
    for (int s = 512; s; s >>= 1) {
        if (threadIdx.x < s) sm[threadIdx.x] = fmaxf(sm[threadIdx.x], sm[threadIdx.x + s]);
        __syncthreads();
    }
    float gmax = sm[0];
    __syncthreads();

    float z = 0.0f;
    for (int i = threadIdx.x; i < nb; i += 1024)
        z += d_blocksum[i] * __expf(d_blockmax[i] - gmax);
    sm[threadIdx.x] = z;
    __syncthreads();
    #pragma unroll
    for (int s = 512; s; s >>= 1) {
        if (threadIdx.x < s) sm[threadIdx.x] += sm[threadIdx.x + s];
        __syncthreads();
    }
    if (threadIdx.x == 0) { d_gmax = gmax; d_invZ = 1.0f / sm[0]; }
}

// TWO CTAs per segment (column split), 64 threads each.
//   CTA 2b+h owns columns [h*256, h*256+256) of segment b — fully independent,
//   zero combine traffic. Halved CTA granularity halves tail/straggler cost
//   and doubles resident CTAs so the serialized prologue hides better.
//   pmax = exp(lmax_seg - gmax); c_i = exp((exp(l_i-gmax)-pmax)*invZ)
//   out half-row = (sum c_i * x_i[cols]) / (sum c_i)
__global__ void __launch_bounds__(64) k_out(const float* __restrict__ x,
                                            float* __restrict__ out) {
    __shared__ float swm[2];
    __shared__ float sc[CHUNK];
    int bb   = blockIdx.x;
    int b    = bb >> 1;
    int half = bb & 1;
    int r0   = d_segstart[b];
    int end  = d_segstart[b + 1];
    int t    = threadIdx.x;          // 0..63
    int col  = t + half * 64;        // float4 index within the 128-float4 row
    float gmax = d_gmax, invZ = d_invZ;

    // segment max logit (both halves compute it; logits are L2-resident)
    float lm = -CUDART_INF_F;
    for (int i = r0 + t; i < end; i += 64) lm = fmaxf(lm, __ldg(&d_logits[i]));
    #pragma unroll
    for (int o = 16; o; o >>= 1) lm = fmaxf(lm, __shfl_xor_sync(0xffffffffu, lm, o));
    if ((t & 31) == 0) swm[t >> 5] = lm;
    __syncthreads();
    float lmax = fmaxf(swm[0], swm[1]);
    float pmax = __expf(lmax - gmax);

    const float4* x4 = (const float4*)x;
    float4 acc = make_float4(0.f, 0.f, 0.f, 0.f);
    float esum = 0.0f;

    for (int base = r0; base < end; base += CHUNK) {
        int len = min(CHUNK, end - base);
        __syncthreads();   // protect sc from previous chunk's readers
        if (t < len) {
            float c = __expf((__expf(__ldg(&d_logits[base + t]) - gmax) - pmax) * invZ);
            sc[t] = c;
            esum += c;     // each row counted exactly once across the block
        }
        __syncthreads();

        const float4* xb = x4 + (size_t)base * 128 + col;
        int j = 0;
        for (; j + 8 <= len; j += 8) {
            float4 v0 = __ldcs(&xb[(size_t)(j)     * 128]);
            float4 v1 = __ldcs(&xb[(size_t)(j + 1) * 128]);
            float4 v2 = __ldcs(&xb[(size_t)(j + 2) * 128]);
            float4 v3 = __ldcs(&xb[(size_t)(j + 3) * 128]);
            float4 v4 = __ldcs(&xb[(size_t)(j + 4) * 128]);
            float4 v5 = __ldcs(&xb[(size_t)(j + 5) * 128]);
            float4 v6 = __ldcs(&xb[(size_t)(j + 6) * 128]);
            float4 v7 = __ldcs(&xb[(size_t)(j + 7) * 128]);
            float c0 = sc[j],     c1 = sc[j + 1], c2 = sc[j + 2], c3 = sc[j + 3];
            float c4 = sc[j + 4], c5 = sc[j + 5], c6 = sc[j + 6], c7 = sc[j + 7];
            acc.x += c0 * v0.x + c1 * v1.x + c2 * v2.x + c3 * v3.x
                   + c4 * v4.x + c5 * v5.x + c6 * v6.x + c7 * v7.x;
            acc.y += c0 * v0.y + c1 * v1.y + c2 * v2.y + c3 * v3.y
                   + c4 * v4.y + c5 * v5.y + c6 * v6.y + c7 * v7.y;
            acc.z += c0 * v0.z + c1 * v1.z + c2 * v2.z + c3 * v3.z
                   + c4 * v4.z + c5 * v5.z + c6 * v6.z + c7 * v7.z;
            acc.w += c0 * v0.w + c1 * v1.w + c2 * v2.w + c3 * v3.w
                   + c4 * v4.w + c5 * v5.w + c6 * v6.w + c7 * v7.w;
        }
        for (; j < len; j++) {
            float c = sc[j];
            float4 v = __ldcs(&xb[(size_t)j * 128]);
            acc.x += c * v.x; acc.y += c * v.y; acc.z += c * v.z; acc.w += c * v.w;
        }
    }

    // block-reduce esum (2 warps)
    #pragma unroll
    for (int o = 16; o; o >>= 1) esum += __shfl_xor_sync(0xffffffffu, esum, o);
    __syncthreads();
    if ((t & 31) == 0) swm[t >> 5] = esum;
    __syncthreads();
    float total = swm[0] + swm[1];
    float invd = 1.0f / total;
    float4 o4 = make_float4(acc.x * invd, acc.y * invd, acc.z * invd, acc.w * invd);
    ((float4*)out)[(size_t)b * 128 + col] = o4;
}

extern "C" void kernel_launch(void* const* d_in, const int* in_sizes, int n_in,
                              void* d_out, int out_size) {
    const float* x     = (const float*)d_in[0];
    const void*  batch = d_in[1];
    const float* W     = (const float*)d_in[2];
    float*       out   = (float*)d_out;

    int n = in_sizes[0] / H;   // rows of x (robust vs. batch dtype width)
    int B = out_size   / H;

    k_seg<<<(n + 255) / 256, 256>>>(batch, n, B);
    int g1 = (n + K1ROWS - 1) / K1ROWS;
    k_logits<<<g1, 256>>>(x, W, n);
    k_reduce<<<1, 1024>>>(g1);
    k_out<<<2 * B, 64>>>(x, out);
}

// round 13
// speedup vs baseline: 1.0243x; 1.0243x over previous
#include <cuda_runtime.h>
#include <math_constants.h>

#define H      512
#define NMAX   262144
#define BMAX   4096
#define K1ROWS 8
#define K1GRID (NMAX / K1ROWS)
#define SPAN   64

// ---- scratch (no allocations allowed) ----
__device__ float d_logits[NMAX];
__device__ float d_w[NMAX];          // final per-row weight c_i / denom_b
__device__ float d_blockmax[K1GRID];
__device__ float d_blocksum[K1GRID];
__device__ int   d_segstart[BMAX + 1];
__device__ float d_gmax;
__device__ float d_invZ;

// Segment starts from sorted batch ids; also zero-init out (poisoned by harness).
// dtype sniff: n even -> int32-view elem n-1 is an int64 high word (==0) iff
// dtype is int64; else it's B-1 != 0.
__global__ void __launch_bounds__(256) k_seg(const void* __restrict__ batch,
                                             int n, int B, float4* __restrict__ out4) {
    int i = blockIdx.x * 256 + threadIdx.x;
    if (i >= n) return;
    int is64 = (((const int*)batch)[n - 1] == 0);   // broadcast L2 hit
    int bc, bp;
    if (is64) {
        bc = (int)__ldg(((const long long*)batch) + i);
        bp = (i == 0) ? -1 : (int)__ldg(((const long long*)batch) + i - 1);
    } else {
        bc = __ldg(((const int*)batch) + i);
        bp = (i == 0) ? -1 : __ldg(((const int*)batch) + i - 1);
    }
    if (bc != bp) d_segstart[bc] = i;
    if (i == n - 1) d_segstart[B] = n;
    // zero out: B*128 float4 spread over n threads
    int tot = B * 128;
    for (int k = i; k < tot; k += n) out4[k] = make_float4(0.f, 0.f, 0.f, 0.f);
}

// Per row: logit = x[row,:] . W  (bias cancels in the global softmax).
// Per block: blockmax + sum(exp(l - blockmax))  (log-sum-exp partials).
__global__ void __launch_bounds__(256) k_logits(const float* __restrict__ x,
                                                const float* __restrict__ W, int n) {
    __shared__ float sW[H];
    __shared__ float smax[K1ROWS];
    int tid = threadIdx.x;
    sW[tid]       = W[tid];
    sW[tid + 256] = W[tid + 256];
    __syncthreads();

    int warp = tid >> 5, lane = tid & 31;
    int row  = blockIdx.x * K1ROWS + warp;
    float v = -CUDART_INF_F;
    if (row < n) {
        const float4* xr = (const float4*)(x + (size_t)row * H);
        const float4* w4 = (const float4*)sW;
        float acc = 0.0f;
        #pragma unroll
        for (int k = 0; k < 4; k++) {
            float4 a = __ldcs(&xr[lane + 32 * k]);
            float4 w = w4[lane + 32 * k];
            acc += a.x * w.x + a.y * w.y + a.z * w.z + a.w * w.w;
        }
        #pragma unroll
        for (int o = 16; o; o >>= 1) acc += __shfl_xor_sync(0xffffffffu, acc, o);
        if (lane == 0) d_logits[row] = acc;
        v = acc;
    }
    if (lane == 0) smax[warp] = v;
    __syncthreads();
    if (tid == 0) {
        float m = smax[0];
        #pragma unroll
        for (int i = 1; i < K1ROWS; i++) m = fmaxf(m, smax[i]);
        float s = 0.0f;
        if (m > -CUDART_INF_F) {
            #pragma unroll
            for (int i = 0; i < K1ROWS; i++) s += __expf(smax[i] - m);
        }
        d_blockmax[blockIdx.x] = m;
        d_blocksum[blockIdx.x] = s;
    }
}

// gmax = max blockmax;  Z = sum blocksum_j * exp(blockmax_j - gmax)
__global__ void __launch_bounds__(1024) k_reduce(int nb) {
    __shared__ float sm[1024];
    float m = -CUDART_INF_F;
    for (int i = threadIdx.x; i < nb; i += 1024) m = fmaxf(m, d_blockmax[i]);
    sm[threadIdx.x] = m;
    __syncthreads();
    #pragma unroll
    for (int s = 512; s; s >>= 1) {
        if (threadIdx.x < s) sm[threadIdx.x] = fmaxf(sm[threadIdx.x], sm[threadIdx.x + s]);
        __syncthreads();
    }
    float gmax = sm[0];
    __syncthreads();

    float z = 0.0f;
    for (int i = threadIdx.x; i < nb; i += 1024)
        z += d_blocksum[i] * __expf(d_blockmax[i] - gmax);
    sm[threadIdx.x] = z;
    __syncthreads();
    #pragma unroll
    for (int s = 512; s; s >>= 1) {
        if (threadIdx.x < s) sm[threadIdx.x] += sm[threadIdx.x + s];
        __syncthreads();
    }
    if (threadIdx.x == 0) { d_gmax = gmax; d_invZ = 1.0f / sm[0]; }
}

// One 64-thread CTA per segment: w_i = c_i / denom_b  (all math hoisted out of
// the streaming kernel). Only touches the 1 MB logits array (L2-resident).
//   pmax = exp(lmax - gmax);  c_i = exp((exp(l_i - gmax) - pmax) * invZ)
__global__ void __launch_bounds__(64) k_coef() {
    __shared__ float sr[2];
    int b   = blockIdx.x;
    int r0  = d_segstart[b];
    int end = d_segstart[b + 1];
    int t   = threadIdx.x;
    float gmax = d_gmax, invZ = d_invZ;

    float lm = -CUDART_INF_F;
    for (int i = r0 + t; i < end; i += 64) lm = fmaxf(lm, d_logits[i]);
    #pragma unroll
    for (int o = 16; o; o >>= 1) lm = fmaxf(lm, __shfl_xor_sync(0xffffffffu, lm, o));
    if ((t & 31) == 0) sr[t >> 5] = lm;
    __syncthreads();
    float pmax = __expf(fmaxf(sr[0], sr[1]) - gmax);
    __syncthreads();

    float s = 0.0f;
    for (int i = r0 + t; i < end; i += 64)
        s += __expf((__expf(d_logits[i] - gmax) - pmax) * invZ);
    #pragma unroll
    for (int o = 16; o; o >>= 1) s += __shfl_xor_sync(0xffffffffu, s, o);
    if ((t & 31) == 0) sr[t >> 5] = s;
    __syncthreads();
    float invd = 1.0f / (sr[0] + sr[1]);

    for (int i = r0 + t; i < end; i += 64)
        d_w[i] = __expf((__expf(d_logits[i] - gmax) - pmax) * invZ) * invd;
}

__device__ __forceinline__ void flush_acc(float* __restrict__ out, int b, int t,
                                          float4 a) {
    float* o = out + (size_t)b * H + t * 4;
    atomicAdd(o + 0, a.x);
    atomicAdd(o + 1, a.y);
    atomicAdd(o + 2, a.z);
    atomicAdd(o + 3, a.w);
}

// UNIFORM streaming kernel, shaped like k_logits: fixed 64-row span per CTA,
// no data-dependent prologue, ONE barrier, pure smem-coeff + 8xLDG.128 + FFMA.
// Segment boundaries inside the span flush the register accumulator with
// atomicAdd (out is pre-zeroed; ~2 flushes/CTA average).
__global__ void __launch_bounds__(128) k_out(const float* __restrict__ x,
                                             const void* __restrict__ batch,
                                             float* __restrict__ out, int n) {
    __shared__ float sw[SPAN];
    __shared__ int   sb[SPAN];
    int row0 = blockIdx.x * SPAN;
    int t = threadIdx.x;

    if (t < SPAN) {
        int i = row0 + t;
        sw[t] = d_w[i];
        int is64 = (((const int*)batch)[n - 1] == 0);
        sb[t] = is64 ? (int)__ldg(((const long long*)batch) + i)
                     : __ldg(((const int*)batch) + i);
    }
    __syncthreads();

    const float4* xb = (const float4*)x + (size_t)row0 * 128 + t;
    float4 acc = make_float4(0.f, 0.f, 0.f, 0.f);
    int cur = sb[0];

    #pragma unroll
    for (int j0 = 0; j0 < SPAN; j0 += 8) {
        float4 v0 = __ldcs(&xb[(size_t)(j0)     * 128]);
        float4 v1 = __ldcs(&xb[(size_t)(j0 + 1) * 128]);
        float4 v2 = __ldcs(&xb[(size_t)(j0 + 2) * 128]);
        float4 v3 = __ldcs(&xb[(size_t)(j0 + 3) * 128]);
        float4 v4 = __ldcs(&xb[(size_t)(j0 + 4) * 128]);
        float4 v5 = __ldcs(&xb[(size_t)(j0 + 5) * 128]);
        float4 v6 = __ldcs(&xb[(size_t)(j0 + 6) * 128]);
        float4 v7 = __ldcs(&xb[(size_t)(j0 + 7) * 128]);
        float4 vv[8] = {v0, v1, v2, v3, v4, v5, v6, v7};
        #pragma unroll
        for (int k = 0; k < 8; k++) {
            int bj = sb[j0 + k];
            if (bj != cur) {                    // rare, predictable branch
                flush_acc(out, cur, t, acc);
                acc = make_float4(0.f, 0.f, 0.f, 0.f);
                cur = bj;
            }
            float c = sw[j0 + k];
            acc.x += c * vv[k].x; acc.y += c * vv[k].y;
            acc.z += c * vv[k].z; acc.w += c * vv[k].w;
        }
    }
    flush_acc(out, cur, t, acc);
}

extern "C" void kernel_launch(void* const* d_in, const int* in_sizes, int n_in,
                              void* d_out, int out_size) {
    const float* x     = (const float*)d_in[0];
    const void*  batch = d_in[1];
    const float* W     = (const float*)d_in[2];
    float*       out   = (float*)d_out;

    int n = in_sizes[0] / H;   // rows of x (robust vs. batch dtype width)
    int B = out_size   / H;

    k_seg<<<(n + 255) / 256, 256>>>(batch, n, B, (float4*)out);
    int g1 = (n + K1ROWS - 1) / K1ROWS;
    k_logits<<<g1, 256>>>(x, W, n);
    k_reduce<<<1, 1024>>>(g1);
    k_coef<<<B, 64>>>();
    k_out<<<n / SPAN, 128>>>(x, batch, out, n);
}